// round 4
// baseline (speedup 1.0000x reference)
#include <cuda_runtime.h>
#include <cuda_bf16.h>
#include <cstdint>

#define B_     4
#define GXF    480            // full output x
#define GXC    360            // compact x (pt_ind in [0,360))
#define GY_    360
#define CIN_   64
#define COUT_  32
#define NPT    480000
#define NVOX   (B_ * GXC * GY_)        // 518400 compact voxels

#define SCAN_TPB  1024
#define SCAN_TILE (SCAN_TPB * 4)                      // 4096
#define NTILE     ((NVOX + SCAN_TILE - 1) / SCAN_TILE) // 127

#define VPB   256                                     // voxels per fused block
#define FUSED_THREADS 512
#define FUSED_SMEM ((VPB * 65 + CIN_ * COUT_ + COUT_) * 4)  // 74880 B

__device__ unsigned int d_cnt[NVOX];
__device__ unsigned int d_cursor[NVOX];
__device__ unsigned int d_seg[NPT];
__device__ unsigned int d_pack[NPT];                  // (idx << 8) | vloc
__device__ unsigned long long d_tileState[NTILE];     // (flag:2)<<62 | value
__device__ unsigned int d_ticket;

__device__ __forceinline__ unsigned int enc_f32(float f) {
    unsigned int u = __float_as_uint(f);
    return (u & 0x80000000u) ? ~u : (u | 0x80000000u);
}
__device__ __forceinline__ float dec_f32(unsigned int u) {
    return (u & 0x80000000u) ? __uint_as_float(u ^ 0x80000000u)
                             : __uint_as_float(~u);
}

// -------- Z: zero counters + scan state + output band x in [360,480) -------
__global__ void zero_kernel(float* __restrict__ out) {
    int g = blockIdx.x * blockDim.x + threadIdx.x;
    if (g < NTILE) d_tileState[g] = 0ull;
    if (g == NTILE) d_ticket = 0u;

    const int nCnt4 = NVOX / 4;                              // 129600
    const int per   = (GXF - GXC) * GY_ / 4;                 // 10800 float4/(b,co)
    const int nBand = B_ * COUT_ * per;                      // 1,382,400
    if (g < nCnt4) {
        reinterpret_cast<uint4*>(d_cnt)[g] = make_uint4(0u,0u,0u,0u);
    } else if (g < nCnt4 + nBand) {
        int gg  = g - nCnt4;
        int c   = gg / per;
        int off = gg % per;
        float4* p = reinterpret_cast<float4*>(
            out + (size_t)c * GXF * GY_ + (size_t)GXC * GY_);
        p[off] = make_float4(0.f, 0.f, 0.f, 0.f);
    }
}

// -------- A: seg id + histogram --------
__global__ void count_kernel(const int* __restrict__ ind,
                             const int* __restrict__ bidx) {
    int i = blockIdx.x * blockDim.x + threadIdx.x;
    if (i >= NPT) return;
    int2 xy = reinterpret_cast<const int2*>(ind)[i];
    int b = bidx[i];
    unsigned int s = (unsigned)((b * GXC + xy.x) * GY_ + xy.y);
    d_seg[i] = s;
    atomicAdd(&d_cnt[s], 1u);
}

// -------- B: single-kernel decoupled-lookback exclusive scan ---------------
__global__ __launch_bounds__(SCAN_TPB) void scan_lookback_kernel() {
    __shared__ unsigned int sWarp[32];
    __shared__ unsigned int sBid;
    __shared__ unsigned int sExcl;
    const int tid = threadIdx.x, lane = tid & 31, wid = tid >> 5;

    if (tid == 0) sBid = atomicAdd(&d_ticket, 1u);
    __syncthreads();
    const int bid  = (int)sBid;
    const int base = bid * SCAN_TILE + tid * 4;

    uint4 x = make_uint4(0u,0u,0u,0u);
    if (base + 3 < NVOX) x = *reinterpret_cast<const uint4*>(d_cnt + base);
    unsigned int s0 = x.x, s1 = s0 + x.y, s2 = s1 + x.z, s3 = s2 + x.w;
    unsigned int tsum = s3;

    unsigned int inc = tsum;
    #pragma unroll
    for (int d = 1; d < 32; d <<= 1) {
        unsigned int v = __shfl_up_sync(0xFFFFFFFFu, inc, d);
        if (lane >= d) inc += v;
    }
    if (lane == 31) sWarp[wid] = inc;
    __syncthreads();
    if (wid == 0) {
        unsigned int v = sWarp[lane];
        #pragma unroll
        for (int d = 1; d < 32; d <<= 1) {
            unsigned int t = __shfl_up_sync(0xFFFFFFFFu, v, d);
            if (lane >= d) v += t;
        }
        sWarp[lane] = v;
    }
    __syncthreads();
    const unsigned int warpOff   = wid ? sWarp[wid - 1] : 0u;
    const unsigned int threadExcl = warpOff + inc - tsum;

    if (tid == 0) {
        unsigned int agg = sWarp[31];
        volatile unsigned long long* st = d_tileState;
        if (bid == 0) {
            st[0] = (2ull << 62) | (unsigned long long)agg;
            sExcl = 0u;
        } else {
            st[bid] = (1ull << 62) | (unsigned long long)agg;
            unsigned int run = 0u;
            int t = bid - 1;
            while (true) {
                unsigned long long s;
                do { s = st[t]; } while ((s >> 62) == 0ull);
                unsigned int val = (unsigned int)(s & 0x3FFFFFFFFFFFFFFFull);
                if ((s >> 62) == 2ull) { run += val; break; }
                run += val; t--;
            }
            sExcl = run;
            st[bid] = (2ull << 62) | (unsigned long long)(run + agg);
        }
    }
    __syncthreads();
    const unsigned int excl = sExcl + threadExcl;
    if (base + 3 < NVOX)
        *reinterpret_cast<uint4*>(d_cursor + base) =
            make_uint4(excl, excl + s0, excl + s1, excl + s2);
}

// -------- C: scatter packed (idx,vloc); cursor -> per-voxel end ----------
__global__ void scatter_kernel() {
    int i = blockIdx.x * blockDim.x + threadIdx.x;
    if (i >= NPT) return;
    unsigned int s = d_seg[i];
    unsigned int pos = atomicAdd(&d_cursor[s], 1u);
    d_pack[pos] = ((unsigned)i << 8) | (s & (VPB - 1u));
}

// -------- D: fused segment-max + Linear(64->32) + ReLU + transposed store --
__global__ __launch_bounds__(FUSED_THREADS) void fused_kernel(
        const float* __restrict__ fea,
        const float* __restrict__ W,
        const float* __restrict__ bias,
        float* __restrict__ out) {
    extern __shared__ unsigned int smem[];
    unsigned int* uPool = smem;                          // VPB*65, 0 == empty
    float* sW = reinterpret_cast<float*>(smem + VPB * 65);
    float* sB = sW + CIN_ * COUT_;
    __shared__ int sS, sE;

    const int tid  = threadIdx.x;
    const int base = blockIdx.x * VPB;
    const int wid  = tid >> 5, lane = tid & 31;

    #pragma unroll
    for (int i = tid; i < CIN_ * COUT_; i += FUSED_THREADS) sW[i] = W[i];
    if (tid < COUT_) sB[tid] = bias[tid];
    #pragma unroll
    for (int i = tid; i < VPB * 65 / 4; i += FUSED_THREADS)
        reinterpret_cast<uint4*>(uPool)[i] = make_uint4(0u,0u,0u,0u);
    if (tid == 0) {
        sE = (int)d_cursor[base + VPB - 1];
        sS = (int)(d_cursor[base] - d_cnt[base]);
    }
    __syncthreads();

    // ---- Phase 1: warp-per-point, conflict-free smem atomic max ----
    {
        const int S = sS, E = sE;
        for (int p = S + wid; p < E; p += FUSED_THREADS / 32) {
            unsigned int u = d_pack[p];
            int vloc = (int)(u & (VPB - 1u));
            int idx  = (int)(u >> 8);
            const float* row = fea + (size_t)idx * CIN_;
            float a = row[lane];
            float b = row[lane + 32];
            atomicMax(&uPool[vloc * 65 + lane],      enc_f32(a));
            atomicMax(&uPool[vloc * 65 + 32 + lane], enc_f32(b));
        }
    }
    __syncthreads();

    // ---- Phase 2: 2 threads/voxel, 16 outputs each, f32x2 FMA ----
    const int v    = tid & (VPB - 1);
    const int half = tid >> 8;                 // VPB == 256
    const int cv   = base + v;
    const int bi   = cv / (GXC * GY_);
    const int rem  = cv % (GXC * GY_);
    const int x    = rem / GY_;
    const int y    = rem % GY_;
    float* optr = out + (((size_t)bi * COUT_ + half * 16) * GXF + x) * GY_ + y;
    const size_t cs = (size_t)GXF * GY_;

    if (uPool[v * 65] == 0u) {                 // empty voxel
        #pragma unroll
        for (int j = 0; j < 16; j++) optr[j * cs] = 0.0f;
        return;
    }

    unsigned long long acc2[8];
    #pragma unroll
    for (int j = 0; j < 8; j++) {
        float blo = sB[half * 16 + 2*j];
        float bhi = sB[half * 16 + 2*j + 1];
        asm("mov.b64 %0, {%1, %2};" : "=l"(acc2[j]) : "f"(blo), "f"(bhi));
    }

    const unsigned int* myRow = &uPool[v * 65];
    #pragma unroll 4
    for (int c = 0; c < CIN_; c++) {
        float pv = dec_f32(myRow[c]);
        unsigned long long pvv;
        asm("mov.b64 %0, {%1, %2};" : "=l"(pvv) : "f"(pv), "f"(pv));
        const ulonglong2* w2 = reinterpret_cast<const ulonglong2*>(
            &sW[c * COUT_ + half * 16]);
        #pragma unroll
        for (int j = 0; j < 4; j++) {
            ulonglong2 w = w2[j];
            asm("fma.rn.f32x2 %0, %1, %2, %3;"
                : "=l"(acc2[2*j])   : "l"(pvv), "l"(w.x), "l"(acc2[2*j]));
            asm("fma.rn.f32x2 %0, %1, %2, %3;"
                : "=l"(acc2[2*j+1]) : "l"(pvv), "l"(w.y), "l"(acc2[2*j+1]));
        }
    }
    #pragma unroll
    for (int j = 0; j < 8; j++) {
        float lo, hi;
        asm("mov.b64 {%0, %1}, %2;" : "=f"(lo), "=f"(hi) : "l"(acc2[j]));
        optr[(2*j)   * cs] = fmaxf(lo, 0.0f);
        optr[(2*j+1) * cs] = fmaxf(hi, 0.0f);
    }
}

extern "C" void kernel_launch(void* const* d_in, const int* in_sizes, int n_in,
                              void* d_out, int out_size) {
    const float* pt_fea   = (const float*)d_in[0];
    const int*   pt_ind   = (const int*)  d_in[1];
    const int*   batch_ix = (const int*)  d_in[2];
    const float* W_comp   = (const float*)d_in[3];
    const float* b_comp   = (const float*)d_in[4];
    float*       out      = (float*)d_out;

    cudaFuncSetAttribute(fused_kernel,
        cudaFuncAttributeMaxDynamicSharedMemorySize, FUSED_SMEM);

    {
        const int nZero = NVOX/4 + B_*COUT_*((GXF-GXC)*GY_/4);
        zero_kernel<<<(nZero + 255)/256, 256>>>(out);
    }
    count_kernel<<<(NPT + 255)/256, 256>>>(pt_ind, batch_ix);
    scan_lookback_kernel<<<NTILE, SCAN_TPB>>>();
    scatter_kernel<<<(NPT + 255)/256, 256>>>();
    fused_kernel<<<NVOX/VPB, FUSED_THREADS, FUSED_SMEM>>>(
        pt_fea, W_comp, b_comp, out);
}